// round 1
// baseline (speedup 1.0000x reference)
#include <cuda_runtime.h>
#include <cuda_fp16.h>
#include <mma.h>

using namespace nvcuda;

// Problem dims
#define BB   128
#define TT   512
#define II   256
#define HH   512
#define KK   768              // I + H
#define COLS 128              // gate columns per CTA (4 gates x 32 hidden)
#define HC   32               // hidden units per CTA
#define CLU  16               // CTAs per cluster
#define ZLD  776              // z row stride in halves (768 + 8 pad)

// SMEM layout (bytes):
//   Ws : 128*768 halves              = 196608
//   Z  : 16*776 halves               =  24832   (offset 196608)
//   PA : 16*128 floats               =   8192   (offset 221440)
// total = 229632  (<= 232448 max dynamic on sm_103a)
#define SMEM_BYTES 229632

// Device-global scratch (static arrays: no runtime allocation)
__device__ __half g_W16[4 * HH * KK];            // [gate][h][k], k contiguous
__device__ __half g_x16[BB * TT * II];           // fp16 copy of x
__device__ __half g_h[2 * BB * HH];              // double-buffered recurrent h

__device__ __forceinline__ uint4 ldcg_v4(const uint4* p) {
    uint4 v;
    asm volatile("ld.global.cg.v4.u32 {%0,%1,%2,%3}, [%4];"
                 : "=r"(v.x), "=r"(v.y), "=r"(v.z), "=r"(v.w) : "l"(p));
    return v;
}
__device__ __forceinline__ void stcg_u32(unsigned* p, unsigned v) {
    asm volatile("st.global.cg.u32 [%0], %1;" :: "l"(p), "r"(v));
}
__device__ __forceinline__ float sigmf(float x) {
    return 1.0f / (1.0f + __expf(-x));
}

// ---------------- prologue kernels ----------------

__global__ void convert_w_kernel(const float* __restrict__ Wf, const float* __restrict__ Wu,
                                 const float* __restrict__ Wc, const float* __restrict__ Wo) {
    const int n = HH * KK;
    for (int i = blockIdx.x * blockDim.x + threadIdx.x; i < n; i += gridDim.x * blockDim.x) {
        g_W16[0 * n + i] = __float2half(Wf[i]);
        g_W16[1 * n + i] = __float2half(Wu[i]);
        g_W16[2 * n + i] = __float2half(Wc[i]);
        g_W16[3 * n + i] = __float2half(Wo[i]);
    }
}

__global__ void convert_x_kernel(const float* __restrict__ x) {
    const int n4 = (BB * TT * II) / 4;
    const float4* x4 = reinterpret_cast<const float4*>(x);
    __half2* o2 = reinterpret_cast<__half2*>(g_x16);
    for (int i = blockIdx.x * blockDim.x + threadIdx.x; i < n4; i += gridDim.x * blockDim.x) {
        float4 v = x4[i];
        o2[2 * i]     = __floats2half2_rn(v.x, v.y);
        o2[2 * i + 1] = __floats2half2_rn(v.z, v.w);
    }
}

// ---------------- persistent LSTM kernel ----------------
// Grid: 128 CTAs = 8 clusters x 16. Cluster owns 16 batch rows; CTA rank r
// owns hidden units [r*32, r*32+32) of all 4 gates (128 gate columns).
// Weights (768x128 fp16) SMEM-resident. h exchanged via L2 with cg ops,
// double-buffered; one cluster barrier per step. c lives in registers.

__global__ void __cluster_dims__(CLU, 1, 1) __launch_bounds__(256, 1)
lstm_kernel(const float* __restrict__ bf, const float* __restrict__ bu,
            const float* __restrict__ bc, const float* __restrict__ bo,
            float* __restrict__ out) {
    extern __shared__ char smem[];
    __half* Ws = reinterpret_cast<__half*>(smem);                    // [c][k] col-major (k contig)
    __half* Z  = Ws + COLS * KK;                                     // [16][ZLD]
    float*  PA = reinterpret_cast<float*>(smem + 221440);            // [16][128]

    const int tid  = threadIdx.x;
    const int warp = tid >> 5;
    const int r          = blockIdx.x & (CLU - 1);     // cluster rank
    const int batch_base = (blockIdx.x >> 4) * 16;     // this cluster's batch slice
    const int hb         = r * HC;                     // hidden base

    // ---- load weight slice into SMEM (once) ----
    {
        const uint4* Wg  = reinterpret_cast<const uint4*>(g_W16);   // 96 uint4 per column
        uint4*       Wsv = reinterpret_cast<uint4*>(Ws);
        for (int idx = tid; idx < COLS * 96; idx += 256) {
            int c = idx / 96, v = idx % 96;
            int g = c >> 5, j = c & 31;
            int gcol = g * HH + hb + j;                 // global column in g_W16
            Wsv[c * 96 + v] = Wg[gcol * 96 + v];
        }
    }

    // ---- per-thread state: each thread owns 2 (batch-row, hidden) cells ----
    const int idx0 = 2 * tid;                 // 0..510 even
    const int i0 = idx0 >> 5;                 // batch row within slice (0..15)
    const int j0 = idx0 & 31;                 // hidden offset (even)
    const int j1 = j0 + 1;
    const int bi = batch_base + i0;           // global batch row

    const float bf0 = bf[hb + j0], bf1 = bf[hb + j1];
    const float bu0 = bu[hb + j0], bu1 = bu[hb + j1];
    const float bc0 = bc[hb + j0], bc1 = bc[hb + j1];
    const float bo0 = bo[hb + j0], bo1 = bo[hb + j1];

    float c0 = 0.0f, c1 = 0.0f;
    float h0v = 0.0f, h1v = 0.0f;

    // zero-init our slice of h buffer 0
    {
        __half2 z2 = __floats2half2_rn(0.0f, 0.0f);
        stcg_u32(reinterpret_cast<unsigned*>(&g_h[(size_t)bi * HH + hb + j0]),
                 *reinterpret_cast<unsigned*>(&z2));
    }
    __syncthreads();
    __threadfence();
    asm volatile("barrier.cluster.arrive.aligned;" ::: "memory");
    asm volatile("barrier.cluster.wait.aligned;" ::: "memory");

    const uint4* xv = reinterpret_cast<const uint4*>(g_x16);
    const uint4* hv = reinterpret_cast<const uint4*>(g_h);
    uint4*       Zv = reinterpret_cast<uint4*>(Z);
    const int cw = warp * 16;                 // this warp's column tile

    for (int t = 0; t < TT; t++) {
        const int pb = t & 1;                 // read buffer
        const int wb = pb ^ 1;                // write buffer

        // ---- gather z = [x_t | h_prev] into SMEM (16 rows x 768, fp16) ----
        #pragma unroll
        for (int q = 0; q < 6; q++) {
            int idx = tid + q * 256;          // 0..1535
            int i = idx / 96, v = idx % 96;   // v: uint4 index within row
            int bg = batch_base + i;
            uint4 val;
            if (v < 32) {                     // x part: 256 halves = 32 uint4
                val = ldcg_v4(&xv[((size_t)bg * TT + t) * 32 + v]);
            } else {                          // h part: 512 halves = 64 uint4
                val = ldcg_v4(&hv[((size_t)pb * BB + bg) * 64 + (v - 32)]);
            }
            Zv[i * 97 + v] = val;             // ZLD=776 halves = 97 uint4
        }
        __syncthreads();

        // ---- GEMM: (16 x 768) @ (768 x 128), warp w -> 16x16 tile ----
        {
            wmma::fragment<wmma::accumulator, 16, 16, 16, float> acc;
            wmma::fill_fragment(acc, 0.0f);
            const __half* wbase = Ws + cw * KK;
            #pragma unroll 4
            for (int kk = 0; kk < 48; kk++) {
                wmma::fragment<wmma::matrix_a, 16, 16, 16, __half, wmma::row_major> fa;
                wmma::fragment<wmma::matrix_b, 16, 16, 16, __half, wmma::col_major> fb;
                wmma::load_matrix_sync(fa, Z + kk * 16, ZLD);
                wmma::load_matrix_sync(fb, wbase + kk * 16, KK);
                wmma::mma_sync(acc, fa, fb, acc);
            }
            wmma::store_matrix_sync(PA + cw, acc, COLS, wmma::mem_row_major);
        }
        __syncthreads();

        // ---- epilogue: gates, state update, write h ----
        {
            const float* row = PA + i0 * COLS;
            float f0 = sigmf(row[j0]       + bf0), f1 = sigmf(row[j1]       + bf1);
            float u0 = sigmf(row[32 + j0]  + bu0), u1 = sigmf(row[32 + j1]  + bu1);
            float gg0 = tanhf(row[64 + j0] + bc0), gg1 = tanhf(row[64 + j1] + bc1);
            float o0 = sigmf(row[96 + j0]  + bo0), o1 = sigmf(row[96 + j1]  + bo1);
            c0 = f0 * c0 + u0 * gg0;
            c1 = f1 * c1 + u1 * gg1;
            h0v = o0 * tanhf(c0);
            h1v = o1 * tanhf(c1);

            __half2 hh = __floats2half2_rn(h0v, h1v);
            stcg_u32(reinterpret_cast<unsigned*>(
                         &g_h[((size_t)wb * BB + bi) * HH + hb + j0]),
                     *reinterpret_cast<unsigned*>(&hh));

            float2 o2 = make_float2(h0v, h1v);
            *reinterpret_cast<float2*>(
                &out[(size_t)t * (BB * HH) + (size_t)bi * HH + hb + j0]) = o2;
        }

        __threadfence();
        asm volatile("barrier.cluster.arrive.aligned;" ::: "memory");
        asm volatile("barrier.cluster.wait.aligned;" ::: "memory");
    }

    // ---- final h, c ----
    const size_t OUT_H = (size_t)TT * BB * HH;
    const size_t OUT_C = OUT_H + (size_t)BB * HH;
    {
        float2 h2 = make_float2(h0v, h1v);
        float2 c2 = make_float2(c0, c1);
        *reinterpret_cast<float2*>(&out[OUT_H + (size_t)bi * HH + hb + j0]) = h2;
        *reinterpret_cast<float2*>(&out[OUT_C + (size_t)bi * HH + hb + j0]) = c2;
    }
}

// ---------------- launcher ----------------

extern "C" void kernel_launch(void* const* d_in, const int* in_sizes, int n_in,
                              void* d_out, int out_size) {
    (void)in_sizes; (void)n_in; (void)out_size;
    const float* x  = (const float*)d_in[0];
    const float* Wf = (const float*)d_in[1];
    const float* bf = (const float*)d_in[2];
    const float* Wu = (const float*)d_in[3];
    const float* bu = (const float*)d_in[4];
    const float* Wc = (const float*)d_in[5];
    const float* bc = (const float*)d_in[6];
    const float* Wo = (const float*)d_in[7];
    const float* bo = (const float*)d_in[8];
    float* out = (float*)d_out;

    cudaFuncSetAttribute(lstm_kernel, cudaFuncAttributeMaxDynamicSharedMemorySize, SMEM_BYTES);
    cudaFuncSetAttribute(lstm_kernel, cudaFuncAttributeNonPortableClusterSizeAllowed, 1);

    convert_w_kernel<<<512, 256>>>(Wf, Wu, Wc, Wo);
    convert_x_kernel<<<2048, 256>>>(x);
    lstm_kernel<<<BB, 256, SMEM_BYTES>>>(bf, bu, bc, bo, out);
}

// round 2
// speedup vs baseline: 1.7301x; 1.7301x over previous
#include <cuda_runtime.h>
#include <cuda_fp16.h>

// Problem dims
#define BB   128
#define TT   512
#define II   256
#define HH   512
#define KK   768              // I + H

// Topology: 8 clusters x 16 CTAs. Cluster owns 16 batch rows.
// CTA rank r owns hidden units [32r, 32r+32) of all 4 gates = 128 gate cols.
// 128 threads = 4 warps; warp w owns 8 hidden units (32 gate cols = 4 n8 tiles).
#define CLU  16
#define NTHR 128

// SMEM: Wfrag 49152 u32 (196608 B) + Afrag 6144 u32 (24576 B) = 221184 B
#define W_U4    12288         // uint4 count of weight fragments per CTA
#define A_U4    1536          // uint4 count of A fragments (16 x 768 fp16)
#define SMEM_BYTES 221184

// Device-global scratch
__device__ unsigned g_Wfrag[16 * W_U4 * 4];      // 3 MB: per-rank fragment-packed weights
__device__ __half   g_x16[(size_t)BB * TT * II]; // fp16 x
__device__ __half   g_h[2 * BB * HH];            // double-buffered recurrent h

__device__ __forceinline__ float sigmf(float x) { return 1.0f / (1.0f + __expf(-x)); }

__device__ __forceinline__ unsigned ldcg_u32(const unsigned* p) {
    unsigned v;
    asm volatile("ld.global.cg.u32 %0, [%1];" : "=r"(v) : "l"(p));
    return v;
}

__device__ __forceinline__ void mma16816(float* c, const uint4& a, unsigned b0, unsigned b1) {
    asm volatile(
        "mma.sync.aligned.m16n8k16.row.col.f32.f16.f16.f32 "
        "{%0,%1,%2,%3}, {%4,%5,%6,%7}, {%8,%9}, {%0,%1,%2,%3};"
        : "+f"(c[0]), "+f"(c[1]), "+f"(c[2]), "+f"(c[3])
        : "r"(a.x), "r"(a.y), "r"(a.z), "r"(a.w), "r"(b0), "r"(b1));
}

// ---------------- prologue kernels ----------------

__global__ void convert_x_kernel(const float* __restrict__ x) {
    const size_t n4 = ((size_t)BB * TT * II) / 4;
    const float4* x4 = reinterpret_cast<const float4*>(x);
    __half2* o2 = reinterpret_cast<__half2*>(g_x16);
    for (size_t i = blockIdx.x * (size_t)blockDim.x + threadIdx.x; i < n4;
         i += (size_t)gridDim.x * blockDim.x) {
        float4 v = x4[i];
        o2[2 * i]     = __floats2half2_rn(v.x, v.y);
        o2[2 * i + 1] = __floats2half2_rn(v.z, v.w);
    }
}

// Pre-shuffle weights into per-thread mma fragment order.
// Column mapping within CTA rank r, warp w, tile t (0..3), n (0..7):
//   j_local = w*8 + (t&1)*4 + (n>>1);  gate = (t>>1)*2 + (n&1)
// B frag (m16n8k16): lane = n*4 + (k2&3); reg = k2>>2 (k2 = k-pair idx in tile)
// u32 index = ((((r*2 + half01)*4 + w)*48 + kt)*32 + lane)*4 + (t&1)*2 + reg
__global__ void convert_wfrag_kernel(const float* __restrict__ Wf, const float* __restrict__ Wu,
                                     const float* __restrict__ Wc, const float* __restrict__ Wo) {
    int id = blockIdx.x * blockDim.x + threadIdx.x;   // (col, kt) pairs
    if (id >= 2048 * 48) return;
    int kt = id % 48;
    int cidx = id / 48;                // gate*512 + jglob
    int gate = cidx >> 9;
    int jglob = cidx & 511;
    const float* W = (gate == 0) ? Wf : (gate == 1) ? Wu : (gate == 2) ? Wc : Wo;

    int r  = jglob >> 5;
    int jl = jglob & 31;
    int w  = jl >> 3;
    int half01 = gate >> 1;
    int tile = half01 * 2 + ((jl >> 2) & 1);
    int n = (jl & 3) * 2 + (gate & 1);

    const float4* src = reinterpret_cast<const float4*>(W + (size_t)jglob * KK + kt * 16);
    float4 v0 = src[0], v1 = src[1], v2 = src[2], v3 = src[3];
    float vv[16] = {v0.x, v0.y, v0.z, v0.w, v1.x, v1.y, v1.z, v1.w,
                    v2.x, v2.y, v2.z, v2.w, v3.x, v3.y, v3.z, v3.w};

    unsigned base = ((((unsigned)(r * 2 + half01) * 4 + w) * 48 + kt) * 32) * 4;
    #pragma unroll
    for (int k2 = 0; k2 < 8; k2++) {
        int reg = k2 >> 2, s = k2 & 3;
        int lane = n * 4 + s;
        int q = (tile & 1) * 2 + reg;
        __half2 hv = __floats2half2_rn(vv[k2 * 2], vv[k2 * 2 + 1]);
        g_Wfrag[base + lane * 4 + q] = *reinterpret_cast<unsigned*>(&hv);
    }
}

// ---------------- persistent LSTM kernel ----------------

__global__ void __cluster_dims__(CLU, 1, 1) __launch_bounds__(NTHR, 1)
lstm_kernel(const float* __restrict__ bf, const float* __restrict__ bu,
            const float* __restrict__ bc, const float* __restrict__ bo,
            float* __restrict__ out) {
    extern __shared__ char smem[];
    uint4* Wu4 = reinterpret_cast<uint4*>(smem);       // 12288 uint4
    uint4* Au4 = Wu4 + W_U4;                           // 1536 uint4 (A fragments)

    const int tid  = threadIdx.x;
    const int w    = tid >> 5;
    const int lane = tid & 31;
    const int r    = blockIdx.x & (CLU - 1);           // cluster rank -> hidden slice
    const int bb   = (blockIdx.x >> 4) * 16;           // batch base
    const int hb   = r * 32;

    // ---- copy this rank's weight fragments into SMEM (once) ----
    {
        const uint4* src = reinterpret_cast<const uint4*>(g_Wfrag) + (size_t)r * W_U4;
        for (int i = tid; i < W_U4; i += NTHR) Wu4[i] = src[i];
    }

    // ---- per-thread cell ownership ----
    const int rA = lane >> 2;                // rows rA, rA+8
    const int jA = w * 8 + (lane & 3);       // hidden offsets jA, jA+4
    const int jB = jA + 4;

    const float bfA = bf[hb + jA], buA = bu[hb + jA], bcA = bc[hb + jA], boA = bo[hb + jA];
    const float bfB = bf[hb + jB], buB = bu[hb + jB], bcB = bc[hb + jB], boB = bo[hb + jB];
    float cst0 = 0.f, cst1 = 0.f, cst2 = 0.f, cst3 = 0.f;
    float h0 = 0.f, h1 = 0.f, h2 = 0.f, h3 = 0.f;

    const unsigned* xsrc = reinterpret_cast<const unsigned*>(g_x16);   // half2 units
    const unsigned* hsrc = reinterpret_cast<const unsigned*>(g_h);     // half2 units
    __half* hdst = g_h;

    // ---- init: zero h-region of Afrag; load+scatter x(0) ----
    {
        uint4 z = make_uint4(0, 0, 0, 0);
        #pragma unroll
        for (int u = 0; u < 8; u++) Au4[512 + tid * 8 + u] = z;
    }
    unsigned xr[16];
    {
        const int kt = tid >> 3;
        #pragma unroll
        for (int u = 0; u < 4; u++) {
            #pragma unroll
            for (int ridx = 0; ridx < 4; ridx++) {
                int row = (tid & 7) + (ridx & 1) * 8;
                int k2  = kt * 8 + u + (ridx >> 1) * 4;
                xr[u * 4 + ridx] = xsrc[((size_t)(bb + row) * TT + 0) * 128 + k2];
            }
        }
        #pragma unroll
        for (int u = 0; u < 4; u++) {
            uint4 v = make_uint4(xr[u * 4], xr[u * 4 + 1], xr[u * 4 + 2], xr[u * 4 + 3]);
            Au4[tid * 4 + u] = v;
        }
    }

    const uint4* Bp0 = Wu4 + (0 * 4 + w) * 1536;
    const uint4* Bp1 = Wu4 + (4 + w) * 1536;

    for (int t = 0; t < TT; t++) {
        __syncthreads();            // Afrag for step t complete (all warps)

        // ---- prefetch x(t+1) into registers (independent of recurrence) ----
        {
            const int tn = (t + 1 < TT) ? (t + 1) : t;
            const int kt = tid >> 3;
            #pragma unroll
            for (int u = 0; u < 4; u++) {
                #pragma unroll
                for (int ridx = 0; ridx < 4; ridx++) {
                    int row = (tid & 7) + (ridx & 1) * 8;
                    int k2  = kt * 8 + u + (ridx >> 1) * 4;
                    xr[u * 4 + ridx] = xsrc[((size_t)(bb + row) * TT + tn) * 128 + k2];
                }
            }
        }

        // ---- GEMM: 16 x 128 x 768, fragment-packed, conflict-free LDS ----
        float acc[4][4];
        #pragma unroll
        for (int i = 0; i < 4; i++)
            #pragma unroll
            for (int q = 0; q < 4; q++) acc[i][q] = 0.f;

        #pragma unroll 8
        for (int kt = 0; kt < 48; kt++) {
            uint4 A   = Au4[kt * 32 + lane];
            uint4 b01 = Bp0[kt * 32 + lane];
            uint4 b23 = Bp1[kt * 32 + lane];
            mma16816(acc[0], A, b01.x, b01.y);
            mma16816(acc[1], A, b01.z, b01.w);
            mma16816(acc[2], A, b23.x, b23.y);
            mma16816(acc[3], A, b23.z, b23.w);
        }

        // ---- epilogue (all in registers: tiles 0/2 -> jA, tiles 1/3 -> jB) ----
        {
            float f, u, g, o;
            f = sigmf(acc[0][0] + bfA); u = sigmf(acc[0][1] + buA);
            g = tanhf(acc[2][0] + bcA); o = sigmf(acc[2][1] + boA);
            cst0 = f * cst0 + u * g;  h0 = o * tanhf(cst0);

            f = sigmf(acc[0][2] + bfA); u = sigmf(acc[0][3] + buA);
            g = tanhf(acc[2][2] + bcA); o = sigmf(acc[2][3] + boA);
            cst1 = f * cst1 + u * g;  h1 = o * tanhf(cst1);

            f = sigmf(acc[1][0] + bfB); u = sigmf(acc[1][1] + buB);
            g = tanhf(acc[3][0] + bcB); o = sigmf(acc[3][1] + boB);
            cst2 = f * cst2 + u * g;  h2 = o * tanhf(cst2);

            f = sigmf(acc[1][2] + bfB); u = sigmf(acc[1][3] + buB);
            g = tanhf(acc[3][2] + bcB); o = sigmf(acc[3][3] + boB);
            cst3 = f * cst3 + u * g;  h3 = o * tanhf(cst3);
        }

        // ---- publish h(t+1) (parity (t+1)&1) + write outputs ----
        {
            const int wb = (t + 1) & 1;
            size_t base0 = ((size_t)wb * BB + bb + rA) * HH + hb;
            size_t base1 = ((size_t)wb * BB + bb + rA + 8) * HH + hb;
            hdst[base0 + jA] = __float2half(h0);
            hdst[base1 + jA] = __float2half(h1);
            hdst[base0 + jB] = __float2half(h2);
            hdst[base1 + jB] = __float2half(h3);

            size_t ob = (size_t)t * (BB * HH);
            out[ob + (size_t)(bb + rA) * HH + hb + jA]     = h0;
            out[ob + (size_t)(bb + rA + 8) * HH + hb + jA] = h1;
            out[ob + (size_t)(bb + rA) * HH + hb + jB]     = h2;
            out[ob + (size_t)(bb + rA + 8) * HH + hb + jB] = h3;
        }

        // ---- cluster barrier: release own h stores, acquire peers' ----
        asm volatile("barrier.cluster.arrive.release.aligned;" ::: "memory");
        asm volatile("barrier.cluster.wait.acquire.aligned;" ::: "memory");

        if (t + 1 < TT) {
            // ---- gather peers' h into Afrag h-region (frag-contiguous STS.128) ----
            {
                const int p  = (t + 1) & 1;
                const int kt = 16 + (tid >> 2);
                #pragma unroll
                for (int u = 0; u < 8; u++) {
                    int l = (tid & 3) * 8 + u;
                    uint4 val;
                    unsigned* vp = reinterpret_cast<unsigned*>(&val);
                    #pragma unroll
                    for (int ridx = 0; ridx < 4; ridx++) {
                        int row = (l >> 2) + (ridx & 1) * 8;
                        int k2h = (kt - 16) * 8 + (l & 3) + (ridx >> 1) * 4;
                        vp[ridx] = ldcg_u32(&hsrc[((size_t)p * BB + bb + row) * 256 + k2h]);
                    }
                    Au4[512 + tid * 8 + u] = val;
                }
            }
            // ---- scatter prefetched x(t+1) ----
            #pragma unroll
            for (int u = 0; u < 4; u++) {
                uint4 v = make_uint4(xr[u * 4], xr[u * 4 + 1], xr[u * 4 + 2], xr[u * 4 + 3]);
                Au4[tid * 4 + u] = v;
            }
        }
    }

    // ---- final h, c ----
    {
        const size_t OUT_H = (size_t)TT * BB * HH;
        const size_t OUT_C = OUT_H + (size_t)BB * HH;
        size_t b0 = (size_t)(bb + rA) * HH + hb;
        size_t b1 = (size_t)(bb + rA + 8) * HH + hb;
        out[OUT_H + b0 + jA] = h0;  out[OUT_H + b1 + jA] = h1;
        out[OUT_H + b0 + jB] = h2;  out[OUT_H + b1 + jB] = h3;
        out[OUT_C + b0 + jA] = cst0; out[OUT_C + b1 + jA] = cst1;
        out[OUT_C + b0 + jB] = cst2; out[OUT_C + b1 + jB] = cst3;
    }
}

// ---------------- launcher ----------------

extern "C" void kernel_launch(void* const* d_in, const int* in_sizes, int n_in,
                              void* d_out, int out_size) {
    (void)in_sizes; (void)n_in; (void)out_size;
    const float* x  = (const float*)d_in[0];
    const float* Wf = (const float*)d_in[1];
    const float* bf = (const float*)d_in[2];
    const float* Wu = (const float*)d_in[3];
    const float* bu = (const float*)d_in[4];
    const float* Wc = (const float*)d_in[5];
    const float* bc = (const float*)d_in[6];
    const float* Wo = (const float*)d_in[7];
    const float* bo = (const float*)d_in[8];
    float* out = (float*)d_out;

    cudaFuncSetAttribute(lstm_kernel, cudaFuncAttributeMaxDynamicSharedMemorySize, SMEM_BYTES);
    cudaFuncSetAttribute(lstm_kernel, cudaFuncAttributeNonPortableClusterSizeAllowed, 1);

    convert_x_kernel<<<2048, 256>>>(x);
    convert_wfrag_kernel<<<(2048 * 48 + 255) / 256, 256>>>(Wf, Wu, Wc, Wo);
    lstm_kernel<<<BB, NTHR, SMEM_BYTES>>>(bf, bu, bc, bo, out);
}

// round 4
// speedup vs baseline: 2.7778x; 1.6056x over previous
#include <cuda_runtime.h>
#include <cuda_fp16.h>
#include <cstdint>

// Problem dims
#define BB 128
#define TT 512
#define II 256
#define HH 512
#define KK 768               // I + H
#define CLU 16

// ---------------- device-global scratch (static; no runtime alloc) ----------------
__device__ __half g_P[(size_t)BB * TT * 2048];   // 268 MB: preact x·Wx^T + bias, [m=b*512+t][gc]
__device__ uint4  g_WhF[16 * 8 * 32 * 32];       // 2 MB : packed Wh B-frags per rank
__device__ uint2  g_WxF[256 * 16 * 32];          // 1 MB : packed Wx B-frags (global n8-tiles)
__device__ uint4  g_hf[2 * 8 * 1024];            // 256 KB: h in A-frag order, double buffered

// ---------------- helpers ----------------
__device__ __forceinline__ uint32_t smem_u32(const void* p) {
    uint32_t a;
    asm("{ .reg .u64 t; cvta.to.shared.u64 t, %1; cvt.u32.u64 %0, t; }" : "=r"(a) : "l"(p));
    return a;
}
__device__ __forceinline__ uint4 ldcg_v4(const uint4* p) {
    uint4 v;
    asm volatile("ld.global.cg.v4.u32 {%0,%1,%2,%3}, [%4];"
                 : "=r"(v.x), "=r"(v.y), "=r"(v.z), "=r"(v.w) : "l"(p));
    return v;
}
__device__ __forceinline__ void mma16816(float* c, const uint4& a, unsigned b0, unsigned b1) {
    asm volatile(
        "mma.sync.aligned.m16n8k16.row.col.f32.f16.f16.f32 "
        "{%0,%1,%2,%3}, {%4,%5,%6,%7}, {%8,%9}, {%0,%1,%2,%3};"
        : "+f"(c[0]), "+f"(c[1]), "+f"(c[2]), "+f"(c[3])
        : "r"(a.x), "r"(a.y), "r"(a.z), "r"(a.w), "r"(b0), "r"(b1));
}
__device__ __forceinline__ void ldmatrix_x4(uint4& a, uint32_t addr) {
    asm volatile("ldmatrix.sync.aligned.m8n8.x4.shared.b16 {%0,%1,%2,%3}, [%4];"
                 : "=r"(a.x), "=r"(a.y), "=r"(a.z), "=r"(a.w) : "r"(addr));
}
__device__ __forceinline__ float sigf(float x) {
    return __fdividef(1.0f, 1.0f + __expf(-x));
}
__device__ __forceinline__ float tanh_fast(float x) {
    float e = __expf(2.0f * x);                  // inf-safe: 1 - 2/(e+1)
    return 1.0f - __fdividef(2.0f, e + 1.0f);
}

// ---------------- pack kernel: Wh + Wx fragment pre-shuffle ----------------
// B-frag (m16n8k16): lane = n*4 + (k2&3); reg = k2>>2; value = half2(W[..,2k2], W[..,2k2+1])
__global__ __launch_bounds__(256) void pack_kernel(
    const float* __restrict__ Wf, const float* __restrict__ Wu,
    const float* __restrict__ Wc, const float* __restrict__ Wo) {
    int gid = blockIdx.x * 256 + threadIdx.x;
    if (blockIdx.x < 256) {
        // ---- Wh part (k in [256,768)) -> per-rank frag layout ----
        int kt = gid & 31, cidx = gid >> 5;          // cidx = gate*512 + jglob
        int gate = cidx >> 9, jglob = cidx & 511;
        const float* W = (gate == 0) ? Wf : (gate == 1) ? Wu : (gate == 2) ? Wc : Wo;
        int r = jglob >> 5, jl = jglob & 31, w = jl >> 3;
        int half01 = gate >> 1, tsel = (jl >> 2) & 1, n = (jl & 3) * 2 + (gate & 1);
        const float4* src = reinterpret_cast<const float4*>(W + (size_t)jglob * KK + 256 + kt * 16);
        float4 v0 = src[0], v1 = src[1], v2 = src[2], v3 = src[3];
        float vv[16] = {v0.x, v0.y, v0.z, v0.w, v1.x, v1.y, v1.z, v1.w,
                        v2.x, v2.y, v2.z, v2.w, v3.x, v3.y, v3.z, v3.w};
        unsigned* dst = reinterpret_cast<unsigned*>(g_WhF);
        unsigned base = (((unsigned)(r * 8 + half01 * 4 + w) * 32 + kt) * 32) * 4;
        #pragma unroll
        for (int k2 = 0; k2 < 8; k2++) {
            int lane = n * 4 + (k2 & 3);
            int q = tsel * 2 + (k2 >> 2);
            __half2 hv = __floats2half2_rn(vv[2 * k2], vv[2 * k2 + 1]);
            dst[base + lane * 4 + q] = *reinterpret_cast<unsigned*>(&hv);
        }
    } else {
        // ---- Wx part (k in [0,256)) -> global n8-tile frag layout ----
        int gid2 = gid - 65536;                      // 0..32767
        int kt = gid2 & 15, gc = gid2 >> 4;          // gc = gate*512 + h
        int gate = gc >> 9;
        const float* W = (gate == 0) ? Wf : (gate == 1) ? Wu : (gate == 2) ? Wc : Wo;
        const float4* src = reinterpret_cast<const float4*>(W + (size_t)(gc & 511) * KK + kt * 16);
        float4 v0 = src[0], v1 = src[1], v2 = src[2], v3 = src[3];
        float vv[16] = {v0.x, v0.y, v0.z, v0.w, v1.x, v1.y, v1.z, v1.w,
                        v2.x, v2.y, v2.z, v2.w, v3.x, v3.y, v3.z, v3.w};
        unsigned* dst = reinterpret_cast<unsigned*>(g_WxF);
        unsigned base = (((unsigned)(gc >> 3) * 16 + kt) * 32) * 2;
        #pragma unroll
        for (int k2 = 0; k2 < 8; k2++) {
            int lane = (gc & 7) * 4 + (k2 & 3);
            int reg = k2 >> 2;
            __half2 hv = __floats2half2_rn(vv[2 * k2], vv[2 * k2 + 1]);
            dst[base + lane * 2 + reg] = *reinterpret_cast<unsigned*>(&hv);
        }
    }
}

// ---------------- prologue GEMM: P = x·Wx^T + bias ----------------
// Grid (16 nb, 512 mb), 256 thr = 8 warps (2M x 4N), warp tile 64x32, K=256.
#define GM_SMEM (128 * 264 * 2)

__global__ __launch_bounds__(256) void gemm_kernel(
    const float* __restrict__ x,
    const float* __restrict__ bf, const float* __restrict__ bu,
    const float* __restrict__ bc, const float* __restrict__ bo) {
    extern __shared__ char smem[];
    __half* As = reinterpret_cast<__half*>(smem);          // [128][264] padded
    const int tid = threadIdx.x;
    const int w = tid >> 5, l = tid & 31;
    const int nb = blockIdx.x, mb = blockIdx.y;

    // load A tile: x rows [mb*128, +128), K=256 fp32 -> fp16 SMEM
    {
        unsigned* As32 = reinterpret_cast<unsigned*>(As);
        #pragma unroll 4
        for (int i = 0; i < 32; i++) {
            int idx = tid + i * 256;
            int row = idx >> 6, c4 = idx & 63;
            float4 v = *reinterpret_cast<const float4*>(&x[((size_t)mb * 128 + row) * 256 + c4 * 4]);
            __half2 h0 = __floats2half2_rn(v.x, v.y);
            __half2 h1 = __floats2half2_rn(v.z, v.w);
            As32[row * 132 + c4 * 2]     = *reinterpret_cast<unsigned*>(&h0);
            As32[row * 132 + c4 * 2 + 1] = *reinterpret_cast<unsigned*>(&h1);
        }
    }
    __syncthreads();

    const int gate = nb >> 2;
    const float* bias = (gate == 0) ? bf : (gate == 1) ? bu : (gate == 2) ? bc : bo;
    float bcol[4][2];
    #pragma unroll
    for (int nt = 0; nt < 4; nt++) {
        int cb = (nb & 3) * 128 + (w & 3) * 32 + nt * 8 + (l & 3) * 2;
        bcol[nt][0] = bias[cb];
        bcol[nt][1] = bias[cb + 1];
    }

    float acc[4][4][4];
    #pragma unroll
    for (int a = 0; a < 4; a++)
        #pragma unroll
        for (int b = 0; b < 4; b++)
            #pragma unroll
            for (int c = 0; c < 4; c++) acc[a][b][c] = 0.f;

    const uint2* Bbase = g_WxF + (size_t)(nb * 16 + (w & 3) * 4) * 16 * 32;
    const uint32_t a_s = smem_u32(As);
    const int mrow0 = (w >> 2) * 64;
    const int m = l >> 3;

    #pragma unroll 2
    for (int kt = 0; kt < 16; kt++) {
        uint2 bfr[4];
        #pragma unroll
        for (int nt = 0; nt < 4; nt++) bfr[nt] = Bbase[(nt * 16 + kt) * 32 + l];
        uint4 afr[4];
        #pragma unroll
        for (int mt = 0; mt < 4; mt++) {
            uint32_t addr = a_s +
                ((mrow0 + mt * 16 + (m & 1) * 8 + (l & 7)) * 264 + kt * 16 + (m >> 1) * 8) * 2;
            ldmatrix_x4(afr[mt], addr);
        }
        #pragma unroll
        for (int mt = 0; mt < 4; mt++)
            #pragma unroll
            for (int nt = 0; nt < 4; nt++)
                mma16816(acc[mt][nt], afr[mt], bfr[nt].x, bfr[nt].y);
    }

    // epilogue: +bias, fp16, scatter into P[m][gc]
    #pragma unroll
    for (int mt = 0; mt < 4; mt++) {
        #pragma unroll
        for (int nt = 0; nt < 4; nt++) {
            int mloc = mrow0 + mt * 16 + (l >> 2);
            size_t m0 = (size_t)mb * 128 + mloc;
            int gc = nb * 128 + (w & 3) * 32 + nt * 8 + (l & 3) * 2;
            #pragma unroll
            for (int cp = 0; cp < 2; cp++) {
                float v0 = acc[mt][nt][cp * 2]     + bcol[nt][0];
                float v1 = acc[mt][nt][cp * 2 + 1] + bcol[nt][1];
                __half2 hv = __floats2half2_rn(v0, v1);
                *reinterpret_cast<unsigned*>(&g_P[(m0 + cp * 8) * 2048 + gc]) =
                    *reinterpret_cast<unsigned*>(&hv);
            }
        }
    }
}

// ---------------- recurrent kernel ----------------
// 8 clusters x 16 CTAs; cluster = 16 batch rows; CTA rank r = hidden [32r,32r+32) all gates.
// 128 threads (4 warps). Weights (Wh frags) SMEM-resident; h exchanged via L2 in A-frag order.
#define L_SMEM (9216 * 16)   // 8192 uint4 Wh + 1024 uint4 A = 147456 B

__global__ void __cluster_dims__(CLU, 1, 1) __launch_bounds__(128, 1)
lstm_kernel(float* __restrict__ out) {
    extern __shared__ char smem[];
    uint4* sW = reinterpret_cast<uint4*>(smem);       // 8192 uint4
    uint4* sA = sW + 8192;                            // 1024 uint4

    const int tid  = threadIdx.x;
    const int w    = tid >> 5;
    const int lane = tid & 31;
    const int r    = blockIdx.x & (CLU - 1);
    const int bgrp = blockIdx.x >> 4;
    const int bb   = bgrp * 16;
    const int hb   = r * 32;

    // Wh frags for this rank -> SMEM (once)
    {
        const uint4* src = g_WhF + (size_t)r * 8192;
        #pragma unroll 8
        for (int i = tid; i < 8192; i += 128) sW[i] = src[i];
    }

    // per-thread ownership: rows {rA, rA+8}, cells {jA, jB}
    const int rA = lane >> 2;
    const int jA = w * 8 + (lane & 3);
    const int jB = jA + 4;

    float cs0 = 0.f, cs1 = 0.f, cs2 = 0.f, cs3 = 0.f;
    float h0 = 0.f, h1 = 0.f, h2 = 0.f, h3 = 0.f;

    const uint4* Bp0 = sW + (0 * 4 + w) * 1024;
    const uint4* Bp1 = sW + (4 + w) * 1024;

    const __half* Pb_row0 = g_P + ((size_t)(bb + rA) * 512) * 2048 + hb;
    const size_t  ROW8    = (size_t)8 * 512 * 2048;
    __half* hf16 = reinterpret_cast<__half*>(g_hf);

    for (int t = 0; t < TT; t++) {
        // ---- prefetch P(t): 16 halves (independent of recurrence) ----
        const __half* Pb  = Pb_row0 + (size_t)t * 2048;
        const __half* Pb8 = Pb + ROW8;
        __half pv[16];
        #pragma unroll
        for (int tp = 0; tp < 2; tp++) {          // gate-pair: 0 -> gates 0/1, 1 -> gates 2/3
            int go = tp * 1024;
            pv[tp * 8 + 0] = __ldg(Pb  + go + jA);
            pv[tp * 8 + 1] = __ldg(Pb  + go + 512 + jA);
            pv[tp * 8 + 2] = __ldg(Pb8 + go + jA);
            pv[tp * 8 + 3] = __ldg(Pb8 + go + 512 + jA);
            pv[tp * 8 + 4] = __ldg(Pb  + go + jB);
            pv[tp * 8 + 5] = __ldg(Pb  + go + 512 + jB);
            pv[tp * 8 + 6] = __ldg(Pb8 + go + jB);
            pv[tp * 8 + 7] = __ldg(Pb8 + go + 512 + jB);
        }

        // ---- A frags: h(t) coalesced from g_hf (frag order), or zeros at t=0 ----
        if (t == 0) {
            uint4 z = make_uint4(0, 0, 0, 0);
            #pragma unroll
            for (int i = 0; i < 8; i++) sA[tid + i * 128] = z;
        } else {
            const uint4* hf = g_hf + ((size_t)(t & 1) * 8 + bgrp) * 1024;
            #pragma unroll
            for (int i = 0; i < 8; i++) sA[tid + i * 128] = ldcg_v4(hf + tid + i * 128);
        }
        __syncthreads();

        // ---- accumulators seeded with P (bias included) ----
        // acc[tile][c]: tile = gatepair*2 + cellsel; c = rowsel*2 + gateparity
        float acc[4][4];
        #pragma unroll
        for (int tile = 0; tile < 4; tile++) {
            int tp = tile >> 1, cs = tile & 1;
            acc[tile][0] = __half2float(pv[tp * 8 + cs * 4 + 0]);
            acc[tile][1] = __half2float(pv[tp * 8 + cs * 4 + 1]);
            acc[tile][2] = __half2float(pv[tp * 8 + cs * 4 + 2]);
            acc[tile][3] = __half2float(pv[tp * 8 + cs * 4 + 3]);
        }

        // ---- GEMM: 16 x 128 x 512 ----
        #pragma unroll 4
        for (int kt = 0; kt < 32; kt++) {
            uint4 A   = sA[kt * 32 + lane];
            uint4 b01 = Bp0[kt * 32 + lane];
            uint4 b23 = Bp1[kt * 32 + lane];
            mma16816(acc[0], A, b01.x, b01.y);
            mma16816(acc[1], A, b01.z, b01.w);
            mma16816(acc[2], A, b23.x, b23.y);
            mma16816(acc[3], A, b23.z, b23.w);
        }
        __syncthreads();   // sA consumed; safe to refill next iter

        // ---- epilogue (registers only) ----
        {
            float f, u, g, o;
            f = sigf(acc[0][0]); u = sigf(acc[0][1]); g = tanh_fast(acc[2][0]); o = sigf(acc[2][1]);
            cs0 = f * cs0 + u * g;  h0 = o * tanh_fast(cs0);
            f = sigf(acc[0][2]); u = sigf(acc[0][3]); g = tanh_fast(acc[2][2]); o = sigf(acc[2][3]);
            cs1 = f * cs1 + u * g;  h1 = o * tanh_fast(cs1);
            f = sigf(acc[1][0]); u = sigf(acc[1][1]); g = tanh_fast(acc[3][0]); o = sigf(acc[3][1]);
            cs2 = f * cs2 + u * g;  h2 = o * tanh_fast(cs2);
            f = sigf(acc[1][2]); u = sigf(acc[1][3]); g = tanh_fast(acc[3][2]); o = sigf(acc[3][3]);
            cs3 = f * cs3 + u * g;  h3 = o * tanh_fast(cs3);
        }

        // ---- publish h(t+1) in A-frag order + write outputs ----
        {
            const int wb = (t + 1) & 1;
            const int hgA = hb + jA, hgB = hb + jB;
            // idx(row, hg) = ((wb*8+bgrp)*1024 + (hg>>4)*32 + (row&7)*4 + ((hg>>1)&3))*8
            //              + ((row>>3) + ((hg>>3)&1)*2)*2 + (hg&1)
            #pragma unroll
            for (int v = 0; v < 4; v++) {
                int row = (v & 1) ? (rA + 8) : rA;
                int hg  = (v & 2) ? hgB : hgA;
                float hv = (v == 0) ? h0 : (v == 1) ? h1 : (v == 2) ? h2 : h3;
                size_t idx = ((size_t)((wb * 8 + bgrp) * 1024
                              + (hg >> 4) * 32 + (row & 7) * 4 + ((hg >> 1) & 3))) * 8
                              + ((row >> 3) + ((hg >> 3) & 1) * 2) * 2 + (hg & 1);
                hf16[idx] = __float2half(hv);
                out[(size_t)t * (BB * HH) + (size_t)(bb + row) * HH + hg] = hv;
            }
        }

        // ---- cluster barrier: release h stores, acquire peers' ----
        asm volatile("barrier.cluster.arrive.release.aligned;" ::: "memory");
        asm volatile("barrier.cluster.wait.acquire.aligned;" ::: "memory");
    }

    // ---- final h, c ----
    {
        const size_t OUT_H = (size_t)TT * BB * HH;
        const size_t OUT_C = OUT_H + (size_t)BB * HH;
        size_t b0 = (size_t)(bb + rA) * HH + hb;
        size_t b1 = (size_t)(bb + rA + 8) * HH + hb;
        out[OUT_H + b0 + jA] = h0;  out[OUT_H + b1 + jA] = h1;
        out[OUT_H + b0 + jB] = h2;  out[OUT_H + b1 + jB] = h3;
        out[OUT_C + b0 + jA] = cs0; out[OUT_C + b1 + jA] = cs1;
        out[OUT_C + b0 + jB] = cs2; out[OUT_C + b1 + jB] = cs3;
    }
}

// ---------------- launcher (3 launches) ----------------

extern "C" void kernel_launch(void* const* d_in, const int* in_sizes, int n_in,
                              void* d_out, int out_size) {
    (void)in_sizes; (void)n_in; (void)out_size;
    const float* x  = (const float*)d_in[0];
    const float* Wf = (const float*)d_in[1];
    const float* bf = (const float*)d_in[2];
    const float* Wu = (const float*)d_in[3];
    const float* bu = (const float*)d_in[4];
    const float* Wc = (const float*)d_in[5];
    const float* bc = (const float*)d_in[6];
    const float* Wo = (const float*)d_in[7];
    const float* bo = (const float*)d_in[8];
    float* out = (float*)d_out;

    cudaFuncSetAttribute(gemm_kernel, cudaFuncAttributeMaxDynamicSharedMemorySize, GM_SMEM);
    cudaFuncSetAttribute(lstm_kernel, cudaFuncAttributeMaxDynamicSharedMemorySize, L_SMEM);
    cudaFuncSetAttribute(lstm_kernel, cudaFuncAttributeNonPortableClusterSizeAllowed, 1);

    pack_kernel<<<384, 256>>>(Wf, Wu, Wc, Wo);
    gemm_kernel<<<dim3(16, 512), 256, GM_SMEM>>>(x, bf, bu, bc, bo);
    lstm_kernel<<<BB, 128, L_SMEM>>>(out);
}

// round 5
// speedup vs baseline: 3.4298x; 1.2347x over previous
#include <cuda_runtime.h>
#include <cuda_fp16.h>
#include <cstdint>

// Problem dims
#define BB 128
#define TT 512
#define II 256
#define HH 512
#define KK 768               // I + H
#define CLU 16

// ---------------- device-global scratch ----------------
__device__ __half g_P[(size_t)BB * TT * 2048];   // preact x·Wx^T + bias, [m=b*512+t][gc]
__device__ uint4  g_WhF2[16 * 8 * 32 * 32];      // 2 MB : Wh B-frags, reg-resident layout
__device__ uint2  g_WxF[256 * 16 * 32];          // 1 MB : Wx B-frags (global n8-tiles)
__device__ uint4  g_hf[2 * 8 * 1024];            // h in A-frag order, double buffered

// ---------------- helpers ----------------
__device__ __forceinline__ uint32_t smem_u32(const void* p) {
    uint32_t a;
    asm("{ .reg .u64 t; cvta.to.shared.u64 t, %1; cvt.u32.u64 %0, t; }" : "=r"(a) : "l"(p));
    return a;
}
__device__ __forceinline__ uint4 ldcg_v4(const uint4* p) {
    uint4 v;
    asm volatile("ld.global.cg.v4.u32 {%0,%1,%2,%3}, [%4];"
                 : "=r"(v.x), "=r"(v.y), "=r"(v.z), "=r"(v.w) : "l"(p));
    return v;
}
__device__ __forceinline__ void mma16816(float* c, const uint4& a, unsigned b0, unsigned b1) {
    asm volatile(
        "mma.sync.aligned.m16n8k16.row.col.f32.f16.f16.f32 "
        "{%0,%1,%2,%3}, {%4,%5,%6,%7}, {%8,%9}, {%0,%1,%2,%3};"
        : "+f"(c[0]), "+f"(c[1]), "+f"(c[2]), "+f"(c[3])
        : "r"(a.x), "r"(a.y), "r"(a.z), "r"(a.w), "r"(b0), "r"(b1));
}
__device__ __forceinline__ void ldmatrix_x4(uint4& a, uint32_t addr) {
    asm volatile("ldmatrix.sync.aligned.m8n8.x4.shared.b16 {%0,%1,%2,%3}, [%4];"
                 : "=r"(a.x), "=r"(a.y), "=r"(a.z), "=r"(a.w) : "r"(addr));
}
__device__ __forceinline__ float sigf(float x) {
    return __fdividef(1.0f, 1.0f + __expf(-x));
}
__device__ __forceinline__ float tanh_fast(float x) {
    float e = __expf(2.0f * x);
    return 1.0f - __fdividef(2.0f, e + 1.0f);
}

// ---------------- pack kernel ----------------
// Blocks 0..511: Wh -> register-resident B-frag layout g_WhF2[r][w][kt][lane].
//   lane: n = lane>>2 (tile col), k2 = (lane&3)+4*reg.  n = cellsub*2 + gsel.
//   uint4 q: tile = q>>1 (0: gates f/u, 1: gates c/o), reg = q&1.
// Blocks 512..639: Wx -> global n8-tile frag layout (unchanged from R4).
__global__ __launch_bounds__(256) void pack_kernel(
    const float* __restrict__ Wf, const float* __restrict__ Wu,
    const float* __restrict__ Wc, const float* __restrict__ Wo) {
    int gid = blockIdx.x * 256 + threadIdx.x;
    if (blockIdx.x < 512) {
        int lane = gid & 31, kt = (gid >> 5) & 31, w = (gid >> 10) & 7, r = (gid >> 13) & 15;
        int gsel = (lane >> 2) & 1;
        int cell = r * 32 + w * 4 + (lane >> 3);
        unsigned* dst = reinterpret_cast<unsigned*>(g_WhF2);
        unsigned base = ((((unsigned)(r * 8 + w) * 32 + kt) * 32 + lane)) * 4;
        #pragma unroll
        for (int q = 0; q < 4; q++) {
            int gate = (q >> 1) * 2 + gsel;
            const float* W = (gate == 0) ? Wf : (gate == 1) ? Wu : (gate == 2) ? Wc : Wo;
            int k2 = (lane & 3) + 4 * (q & 1);
            int kcol = 256 + kt * 16 + k2 * 2;
            __half2 hv = __floats2half2_rn(W[(size_t)cell * KK + kcol],
                                           W[(size_t)cell * KK + kcol + 1]);
            dst[base + q] = *reinterpret_cast<unsigned*>(&hv);
        }
    } else {
        int gid2 = gid - 512 * 256;                  // 0..32767
        int kt = gid2 & 15, gc = gid2 >> 4;
        int gate = gc >> 9;
        const float* W = (gate == 0) ? Wf : (gate == 1) ? Wu : (gate == 2) ? Wc : Wo;
        const float4* src = reinterpret_cast<const float4*>(W + (size_t)(gc & 511) * KK + kt * 16);
        float4 v0 = src[0], v1 = src[1], v2 = src[2], v3 = src[3];
        float vv[16] = {v0.x, v0.y, v0.z, v0.w, v1.x, v1.y, v1.z, v1.w,
                        v2.x, v2.y, v2.z, v2.w, v3.x, v3.y, v3.z, v3.w};
        unsigned* dst = reinterpret_cast<unsigned*>(g_WxF);
        unsigned base = (((unsigned)(gc >> 3) * 16 + kt) * 32) * 2;
        #pragma unroll
        for (int k2 = 0; k2 < 8; k2++) {
            int lane = (gc & 7) * 4 + (k2 & 3);
            int reg = k2 >> 2;
            __half2 hv = __floats2half2_rn(vv[2 * k2], vv[2 * k2 + 1]);
            dst[base + lane * 2 + reg] = *reinterpret_cast<unsigned*>(&hv);
        }
    }
}

// ---------------- prologue GEMM: P = x·Wx^T + bias (unchanged from R4) ----------------
#define GM_SMEM (128 * 264 * 2)

__global__ __launch_bounds__(256) void gemm_kernel(
    const float* __restrict__ x,
    const float* __restrict__ bf, const float* __restrict__ bu,
    const float* __restrict__ bc, const float* __restrict__ bo) {
    extern __shared__ char smem[];
    __half* As = reinterpret_cast<__half*>(smem);
    const int tid = threadIdx.x;
    const int w = tid >> 5, l = tid & 31;
    const int nb = blockIdx.x, mb = blockIdx.y;

    {
        unsigned* As32 = reinterpret_cast<unsigned*>(As);
        #pragma unroll 4
        for (int i = 0; i < 32; i++) {
            int idx = tid + i * 256;
            int row = idx >> 6, c4 = idx & 63;
            float4 v = *reinterpret_cast<const float4*>(&x[((size_t)mb * 128 + row) * 256 + c4 * 4]);
            __half2 h0 = __floats2half2_rn(v.x, v.y);
            __half2 h1 = __floats2half2_rn(v.z, v.w);
            As32[row * 132 + c4 * 2]     = *reinterpret_cast<unsigned*>(&h0);
            As32[row * 132 + c4 * 2 + 1] = *reinterpret_cast<unsigned*>(&h1);
        }
    }
    __syncthreads();

    const int gate = nb >> 2;
    const float* bias = (gate == 0) ? bf : (gate == 1) ? bu : (gate == 2) ? bc : bo;
    float bcol[4][2];
    #pragma unroll
    for (int nt = 0; nt < 4; nt++) {
        int cb = (nb & 3) * 128 + (w & 3) * 32 + nt * 8 + (l & 3) * 2;
        bcol[nt][0] = bias[cb];
        bcol[nt][1] = bias[cb + 1];
    }

    float acc[4][4][4];
    #pragma unroll
    for (int a = 0; a < 4; a++)
        #pragma unroll
        for (int b = 0; b < 4; b++)
            #pragma unroll
            for (int c = 0; c < 4; c++) acc[a][b][c] = 0.f;

    const uint2* Bbase = g_WxF + (size_t)(nb * 16 + (w & 3) * 4) * 16 * 32;
    const uint32_t a_s = smem_u32(As);
    const int mrow0 = (w >> 2) * 64;
    const int m = l >> 3;

    #pragma unroll 2
    for (int kt = 0; kt < 16; kt++) {
        uint2 bfr[4];
        #pragma unroll
        for (int nt = 0; nt < 4; nt++) bfr[nt] = Bbase[(nt * 16 + kt) * 32 + l];
        uint4 afr[4];
        #pragma unroll
        for (int mt = 0; mt < 4; mt++) {
            uint32_t addr = a_s +
                ((mrow0 + mt * 16 + (m & 1) * 8 + (l & 7)) * 264 + kt * 16 + (m >> 1) * 8) * 2;
            ldmatrix_x4(afr[mt], addr);
        }
        #pragma unroll
        for (int mt = 0; mt < 4; mt++)
            #pragma unroll
            for (int nt = 0; nt < 4; nt++)
                mma16816(acc[mt][nt], afr[mt], bfr[nt].x, bfr[nt].y);
    }

    #pragma unroll
    for (int mt = 0; mt < 4; mt++) {
        #pragma unroll
        for (int nt = 0; nt < 4; nt++) {
            int mloc = mrow0 + mt * 16 + (l >> 2);
            size_t m0 = (size_t)mb * 128 + mloc;
            int gc = nb * 128 + (w & 3) * 32 + nt * 8 + (l & 3) * 2;
            #pragma unroll
            for (int cp = 0; cp < 2; cp++) {
                float v0 = acc[mt][nt][cp * 2]     + bcol[nt][0];
                float v1 = acc[mt][nt][cp * 2 + 1] + bcol[nt][1];
                __half2 hv = __floats2half2_rn(v0, v1);
                *reinterpret_cast<unsigned*>(&g_P[(m0 + cp * 8) * 2048 + gc]) =
                    *reinterpret_cast<unsigned*>(&hv);
            }
        }
    }
}

// ---------------- recurrent kernel ----------------
// 8 clusters x 16 CTAs; 256 threads = 8 warps. Warp w owns cells w*4..w*4+3
// (2 n8-tiles: gates f/u and c/o). Wh B-frags live in 128 registers/thread.
#define L_SMEM 16384

__global__ void __cluster_dims__(CLU, 1, 1) __launch_bounds__(256, 1)
lstm_kernel(float* __restrict__ out) {
    extern __shared__ char smem[];
    uint4* sA = reinterpret_cast<uint4*>(smem);       // 1024 uint4 = h A-frags

    const int tid  = threadIdx.x;
    const int w    = tid >> 5;
    const int lane = tid & 31;
    const int r    = blockIdx.x & (CLU - 1);
    const int bgrp = blockIdx.x >> 4;
    const int bb   = bgrp * 16;
    const int hb   = r * 32;

    // ---- weights into registers (once) ----
    uint4 wb_[32];
    {
        const uint4* src = g_WhF2 + ((size_t)(r * 8 + w) * 32) * 32;
        #pragma unroll
        for (int kt = 0; kt < 32; kt++) wb_[kt] = src[kt * 32 + lane];
    }

    // ---- per-thread ownership: rows {rA, rA+8}, cell hg ----
    const int rA = lane >> 2;
    const int hg = hb + w * 4 + (lane & 3);

    float cs0 = 0.f, cs1 = 0.f, hv0 = 0.f, hv1 = 0.f;

    const __half* P0 = g_P + ((size_t)(bb + rA) * 512) * 2048;       // row rA
    const __half* P8 = g_P + ((size_t)(bb + rA + 8) * 512) * 2048;   // row rA+8
    __half* hf16 = reinterpret_cast<__half*>(g_hf);

    // pv: {f@rA, u@rA, f@rA8, u@rA8, g@rA, o@rA, g@rA8, o@rA8}
    float pv[8];
    {
        const __half* p0 = P0;  const __half* p8 = P8;
        pv[0] = __half2float(__ldg(p0 + hg));
        pv[1] = __half2float(__ldg(p0 + 512 + hg));
        pv[2] = __half2float(__ldg(p8 + hg));
        pv[3] = __half2float(__ldg(p8 + 512 + hg));
        pv[4] = __half2float(__ldg(p0 + 1024 + hg));
        pv[5] = __half2float(__ldg(p0 + 1536 + hg));
        pv[6] = __half2float(__ldg(p8 + 1024 + hg));
        pv[7] = __half2float(__ldg(p8 + 1536 + hg));
    }

    for (int t = 0; t < TT; t++) {
        // ---- stage A frags: h(t) from g_hf (frag order), zeros at t=0 ----
        if (t == 0) {
            uint4 z = make_uint4(0, 0, 0, 0);
            #pragma unroll
            for (int i = 0; i < 4; i++) sA[tid + i * 256] = z;
        } else {
            const uint4* hf = g_hf + ((size_t)(t & 1) * 8 + bgrp) * 1024;
            #pragma unroll
            for (int i = 0; i < 4; i++) sA[tid + i * 256] = ldcg_v4(hf + tid + i * 256);
        }
        __syncthreads();

        // ---- accumulators seeded with P(t) ----
        float acc0[4] = {pv[0], pv[1], pv[2], pv[3]};
        float acc1[4] = {pv[4], pv[5], pv[6], pv[7]};

        // ---- GEMM: 16 x 128 x 512, B in registers ----
        #pragma unroll
        for (int kt = 0; kt < 32; kt++) {
            uint4 A = sA[kt * 32 + lane];
            mma16816(acc0, A, wb_[kt].x, wb_[kt].y);
            mma16816(acc1, A, wb_[kt].z, wb_[kt].w);
        }
        __syncthreads();

        // ---- epilogue: 2 cells ----
        {
            float f, u, g, o;
            f = sigf(acc0[0]); u = sigf(acc0[1]); g = tanh_fast(acc1[0]); o = sigf(acc1[1]);
            cs0 = f * cs0 + u * g;  hv0 = o * tanh_fast(cs0);
            f = sigf(acc0[2]); u = sigf(acc0[3]); g = tanh_fast(acc1[2]); o = sigf(acc1[3]);
            cs1 = f * cs1 + u * g;  hv1 = o * tanh_fast(cs1);
        }

        // ---- publish h(t+1) in A-frag order + outputs ----
        {
            const int wb2 = (t + 1) & 1;
            const int blk = (wb2 * 8 + bgrp) * 1024;
            // idx(row,hg) = (blk + (hg>>4)*32 + (row&7)*4 + ((hg>>1)&3))*8
            //             + ((row>>3) + ((hg>>3)&1)*2)*2 + (hg&1)
            size_t i0 = ((size_t)(blk + (hg >> 4) * 32 + rA * 4 + ((hg >> 1) & 3))) * 8
                        + (((hg >> 3) & 1) * 2) * 2 + (hg & 1);
            hf16[i0] = __float2half(hv0);
            hf16[i0 + 2] = __float2half(hv1);          // row+8: (row>>3)=1 -> +2 halves
            out[(size_t)t * (BB * HH) + (size_t)(bb + rA) * HH + hg] = hv0;
            out[(size_t)t * (BB * HH) + (size_t)(bb + rA + 8) * HH + hg] = hv1;
        }

        asm volatile("barrier.cluster.arrive.release.aligned;" ::: "memory");

        // ---- prefetch P(t+1) under the barrier wait ----
        if (t + 1 < TT) {
            const __half* p0 = P0 + (size_t)(t + 1) * 2048;
            const __half* p8 = P8 + (size_t)(t + 1) * 2048;
            pv[0] = __half2float(__ldg(p0 + hg));
            pv[1] = __half2float(__ldg(p0 + 512 + hg));
            pv[2] = __half2float(__ldg(p8 + hg));
            pv[3] = __half2float(__ldg(p8 + 512 + hg));
            pv[4] = __half2float(__ldg(p0 + 1024 + hg));
            pv[5] = __half2float(__ldg(p0 + 1536 + hg));
            pv[6] = __half2float(__ldg(p8 + 1024 + hg));
            pv[7] = __half2float(__ldg(p8 + 1536 + hg));
        }

        asm volatile("barrier.cluster.wait.acquire.aligned;" ::: "memory");
    }

    // ---- final h, c ----
    {
        const size_t OUT_H = (size_t)TT * BB * HH;
        const size_t OUT_C = OUT_H + (size_t)BB * HH;
        size_t b0 = (size_t)(bb + rA) * HH + hg;
        size_t b1 = (size_t)(bb + rA + 8) * HH + hg;
        out[OUT_H + b0] = hv0;  out[OUT_H + b1] = hv1;
        out[OUT_C + b0] = cs0;  out[OUT_C + b1] = cs1;
    }
}

// ---------------- launcher ----------------

extern "C" void kernel_launch(void* const* d_in, const int* in_sizes, int n_in,
                              void* d_out, int out_size) {
    (void)in_sizes; (void)n_in; (void)out_size;
    const float* x  = (const float*)d_in[0];
    const float* Wf = (const float*)d_in[1];
    const float* bf = (const float*)d_in[2];
    const float* Wu = (const float*)d_in[3];
    const float* bu = (const float*)d_in[4];
    const float* Wc = (const float*)d_in[5];
    const float* bc = (const float*)d_in[6];
    const float* Wo = (const float*)d_in[7];
    const float* bo = (const float*)d_in[8];
    float* out = (float*)d_out;

    cudaFuncSetAttribute(gemm_kernel, cudaFuncAttributeMaxDynamicSharedMemorySize, GM_SMEM);
    cudaFuncSetAttribute(lstm_kernel, cudaFuncAttributeMaxDynamicSharedMemorySize, L_SMEM);
    cudaFuncSetAttribute(lstm_kernel, cudaFuncAttributeNonPortableClusterSizeAllowed, 1);

    pack_kernel<<<640, 256>>>(Wf, Wu, Wc, Wo);
    gemm_kernel<<<dim3(16, 512), 256, GM_SMEM>>>(x, bf, bu, bc, bo);
    lstm_kernel<<<BB, 256, L_SMEM>>>(out);
}

// round 6
// speedup vs baseline: 3.4385x; 1.0026x over previous
#include <cuda_runtime.h>
#include <cuda_fp16.h>
#include <cstdint>

// Problem dims
#define BB 128
#define TT 512
#define II 256
#define HH 512
#define KK 768               // I + H
#define CLU 16

// ---------------- device-global scratch ----------------
__device__ __half g_P[(size_t)BB * TT * 2048];   // preact x·Wx^T + bias, [m=b*512+t][gc]
__device__ uint4  g_WhF2[16 * 8 * 32 * 32];      // 2 MB : Wh B-frags, reg-resident layout
__device__ uint2  g_WxF[256 * 16 * 32];          // 1 MB : Wx B-frags (global n8-tiles)
__device__ uint4  g_hf[2 * 8 * 1024];            // h in A-frag order, double buffered

// ---------------- helpers ----------------
__device__ __forceinline__ uint32_t smem_u32(const void* p) {
    uint32_t a;
    asm("{ .reg .u64 t; cvta.to.shared.u64 t, %1; cvt.u32.u64 %0, t; }" : "=r"(a) : "l"(p));
    return a;
}
__device__ __forceinline__ uint4 ldcg_v4(const uint4* p) {
    uint4 v;
    asm volatile("ld.global.cg.v4.u32 {%0,%1,%2,%3}, [%4];"
                 : "=r"(v.x), "=r"(v.y), "=r"(v.z), "=r"(v.w) : "l"(p));
    return v;
}
__device__ __forceinline__ void mma16816(float* c, const uint4& a, unsigned b0, unsigned b1) {
    asm volatile(
        "mma.sync.aligned.m16n8k16.row.col.f32.f16.f16.f32 "
        "{%0,%1,%2,%3}, {%4,%5,%6,%7}, {%8,%9}, {%0,%1,%2,%3};"
        : "+f"(c[0]), "+f"(c[1]), "+f"(c[2]), "+f"(c[3])
        : "r"(a.x), "r"(a.y), "r"(a.z), "r"(a.w), "r"(b0), "r"(b1));
}
__device__ __forceinline__ void ldmatrix_x4(uint4& a, uint32_t addr) {
    asm volatile("ldmatrix.sync.aligned.m8n8.x4.shared.b16 {%0,%1,%2,%3}, [%4];"
                 : "=r"(a.x), "=r"(a.y), "=r"(a.z), "=r"(a.w) : "r"(addr));
}
__device__ __forceinline__ float sigf(float x) {
    return __fdividef(1.0f, 1.0f + __expf(-x));
}
__device__ __forceinline__ float tanh_fast(float x) {
    float e = __expf(2.0f * x);
    return 1.0f - __fdividef(2.0f, e + 1.0f);
}

// ---------------- pack kernel (unchanged from R5) ----------------
__global__ __launch_bounds__(256) void pack_kernel(
    const float* __restrict__ Wf, const float* __restrict__ Wu,
    const float* __restrict__ Wc, const float* __restrict__ Wo) {
    int gid = blockIdx.x * 256 + threadIdx.x;
    if (blockIdx.x < 512) {
        int lane = gid & 31, kt = (gid >> 5) & 31, w = (gid >> 10) & 7, r = (gid >> 13) & 15;
        int gsel = (lane >> 2) & 1;
        int cell = r * 32 + w * 4 + (lane >> 3);
        unsigned* dst = reinterpret_cast<unsigned*>(g_WhF2);
        unsigned base = ((((unsigned)(r * 8 + w) * 32 + kt) * 32 + lane)) * 4;
        #pragma unroll
        for (int q = 0; q < 4; q++) {
            int gate = (q >> 1) * 2 + gsel;
            const float* W = (gate == 0) ? Wf : (gate == 1) ? Wu : (gate == 2) ? Wc : Wo;
            int k2 = (lane & 3) + 4 * (q & 1);
            int kcol = 256 + kt * 16 + k2 * 2;
            __half2 hv = __floats2half2_rn(W[(size_t)cell * KK + kcol],
                                           W[(size_t)cell * KK + kcol + 1]);
            dst[base + q] = *reinterpret_cast<unsigned*>(&hv);
        }
    } else {
        int gid2 = gid - 512 * 256;
        int kt = gid2 & 15, gc = gid2 >> 4;
        int gate = gc >> 9;
        const float* W = (gate == 0) ? Wf : (gate == 1) ? Wu : (gate == 2) ? Wc : Wo;
        const float4* src = reinterpret_cast<const float4*>(W + (size_t)(gc & 511) * KK + kt * 16);
        float4 v0 = src[0], v1 = src[1], v2 = src[2], v3 = src[3];
        float vv[16] = {v0.x, v0.y, v0.z, v0.w, v1.x, v1.y, v1.z, v1.w,
                        v2.x, v2.y, v2.z, v2.w, v3.x, v3.y, v3.z, v3.w};
        unsigned* dst = reinterpret_cast<unsigned*>(g_WxF);
        unsigned base = (((unsigned)(gc >> 3) * 16 + kt) * 32) * 2;
        #pragma unroll
        for (int k2 = 0; k2 < 8; k2++) {
            int lane = (gc & 7) * 4 + (k2 & 3);
            int reg = k2 >> 2;
            __half2 hv = __floats2half2_rn(vv[2 * k2], vv[2 * k2 + 1]);
            dst[base + lane * 2 + reg] = *reinterpret_cast<unsigned*>(&hv);
        }
    }
}

// ---------------- prologue GEMM: P = x·Wx^T + bias (unchanged) ----------------
#define GM_SMEM (128 * 264 * 2)

__global__ __launch_bounds__(256) void gemm_kernel(
    const float* __restrict__ x,
    const float* __restrict__ bf, const float* __restrict__ bu,
    const float* __restrict__ bc, const float* __restrict__ bo) {
    extern __shared__ char smem[];
    __half* As = reinterpret_cast<__half*>(smem);
    const int tid = threadIdx.x;
    const int w = tid >> 5, l = tid & 31;
    const int nb = blockIdx.x, mb = blockIdx.y;

    {
        unsigned* As32 = reinterpret_cast<unsigned*>(As);
        #pragma unroll 4
        for (int i = 0; i < 32; i++) {
            int idx = tid + i * 256;
            int row = idx >> 6, c4 = idx & 63;
            float4 v = *reinterpret_cast<const float4*>(&x[((size_t)mb * 128 + row) * 256 + c4 * 4]);
            __half2 h0 = __floats2half2_rn(v.x, v.y);
            __half2 h1 = __floats2half2_rn(v.z, v.w);
            As32[row * 132 + c4 * 2]     = *reinterpret_cast<unsigned*>(&h0);
            As32[row * 132 + c4 * 2 + 1] = *reinterpret_cast<unsigned*>(&h1);
        }
    }
    __syncthreads();

    const int gate = nb >> 2;
    const float* bias = (gate == 0) ? bf : (gate == 1) ? bu : (gate == 2) ? bc : bo;
    float bcol[4][2];
    #pragma unroll
    for (int nt = 0; nt < 4; nt++) {
        int cb = (nb & 3) * 128 + (w & 3) * 32 + nt * 8 + (l & 3) * 2;
        bcol[nt][0] = bias[cb];
        bcol[nt][1] = bias[cb + 1];
    }

    float acc[4][4][4];
    #pragma unroll
    for (int a = 0; a < 4; a++)
        #pragma unroll
        for (int b = 0; b < 4; b++)
            #pragma unroll
            for (int c = 0; c < 4; c++) acc[a][b][c] = 0.f;

    const uint2* Bbase = g_WxF + (size_t)(nb * 16 + (w & 3) * 4) * 16 * 32;
    const uint32_t a_s = smem_u32(As);
    const int mrow0 = (w >> 2) * 64;
    const int m = l >> 3;

    #pragma unroll 2
    for (int kt = 0; kt < 16; kt++) {
        uint2 bfr[4];
        #pragma unroll
        for (int nt = 0; nt < 4; nt++) bfr[nt] = Bbase[(nt * 16 + kt) * 32 + l];
        uint4 afr[4];
        #pragma unroll
        for (int mt = 0; mt < 4; mt++) {
            uint32_t addr = a_s +
                ((mrow0 + mt * 16 + (m & 1) * 8 + (l & 7)) * 264 + kt * 16 + (m >> 1) * 8) * 2;
            ldmatrix_x4(afr[mt], addr);
        }
        #pragma unroll
        for (int mt = 0; mt < 4; mt++)
            #pragma unroll
            for (int nt = 0; nt < 4; nt++)
                mma16816(acc[mt][nt], afr[mt], bfr[nt].x, bfr[nt].y);
    }

    #pragma unroll
    for (int mt = 0; mt < 4; mt++) {
        #pragma unroll
        for (int nt = 0; nt < 4; nt++) {
            int mloc = mrow0 + mt * 16 + (l >> 2);
            size_t m0 = (size_t)mb * 128 + mloc;
            int gc = nb * 128 + (w & 3) * 32 + nt * 8 + (l & 3) * 2;
            #pragma unroll
            for (int cp = 0; cp < 2; cp++) {
                float v0 = acc[mt][nt][cp * 2]     + bcol[nt][0];
                float v1 = acc[mt][nt][cp * 2 + 1] + bcol[nt][1];
                __half2 hv = __floats2half2_rn(v0, v1);
                *reinterpret_cast<unsigned*>(&g_P[(m0 + cp * 8) * 2048 + gc]) =
                    *reinterpret_cast<unsigned*>(&hv);
            }
        }
    }
}

// ---------------- recurrent kernel ----------------
// 8 clusters x 16 CTAs; 256 threads = 8 warps. Warp w owns cells w*4..w*4+3.
// Wh B-frags in registers. 4 independent HMMA chains/thread; pipelined A LDS;
// single __syncthreads per step (post-MMA sync subsumed by cluster barrier).
#define L_SMEM 16384

__global__ void __cluster_dims__(CLU, 1, 1) __launch_bounds__(256, 1)
lstm_kernel(float* __restrict__ out) {
    extern __shared__ char smem[];
    uint4* sA = reinterpret_cast<uint4*>(smem);       // 1024 uint4 = h A-frags

    const int tid  = threadIdx.x;
    const int w    = tid >> 5;
    const int lane = tid & 31;
    const int r    = blockIdx.x & (CLU - 1);
    const int bgrp = blockIdx.x >> 4;
    const int bb   = bgrp * 16;
    const int hb   = r * 32;

    // ---- weights into registers (once) ----
    uint4 wb_[32];
    {
        const uint4* src = g_WhF2 + ((size_t)(r * 8 + w) * 32) * 32;
        #pragma unroll
        for (int kt = 0; kt < 32; kt++) wb_[kt] = src[kt * 32 + lane];
    }

    // ---- per-thread ownership: rows {rA, rA+8}, cell hg ----
    const int rA = lane >> 2;
    const int hg = hb + w * 4 + (lane & 3);

    float cs0 = 0.f, cs1 = 0.f, hv0 = 0.f, hv1 = 0.f;

    const __half* P0 = g_P + ((size_t)(bb + rA) * 512) * 2048;
    const __half* P8 = g_P + ((size_t)(bb + rA + 8) * 512) * 2048;
    __half* hf16 = reinterpret_cast<__half*>(g_hf);

    // pv: {f@rA, u@rA, f@rA8, u@rA8, g@rA, o@rA, g@rA8, o@rA8}
    float pv[8];
    {
        pv[0] = __half2float(__ldg(P0 + hg));
        pv[1] = __half2float(__ldg(P0 + 512 + hg));
        pv[2] = __half2float(__ldg(P8 + hg));
        pv[3] = __half2float(__ldg(P8 + 512 + hg));
        pv[4] = __half2float(__ldg(P0 + 1024 + hg));
        pv[5] = __half2float(__ldg(P0 + 1536 + hg));
        pv[6] = __half2float(__ldg(P8 + 1024 + hg));
        pv[7] = __half2float(__ldg(P8 + 1536 + hg));
    }

    for (int t = 0; t < TT; t++) {
        // ---- stage A frags: h(t) from g_hf (frag order), zeros at t=0 ----
        // Safe without post-MMA sync: cluster barrier at end of prev iter
        // guarantees every warp finished its MMA reads before arriving.
        if (t == 0) {
            uint4 z = make_uint4(0, 0, 0, 0);
            #pragma unroll
            for (int i = 0; i < 4; i++) sA[tid + i * 256] = z;
        } else {
            const uint4* hf = g_hf + ((size_t)(t & 1) * 8 + bgrp) * 1024;
            #pragma unroll
            for (int i = 0; i < 4; i++) sA[tid + i * 256] = ldcg_v4(hf + tid + i * 256);
        }
        __syncthreads();

        // ---- 4 independent accumulator chains, seeded with P(t) ----
        float a0e[4] = {pv[0], pv[1], pv[2], pv[3]};
        float a1e[4] = {pv[4], pv[5], pv[6], pv[7]};
        float a0o[4] = {0.f, 0.f, 0.f, 0.f};
        float a1o[4] = {0.f, 0.f, 0.f, 0.f};

        // ---- GEMM: 16 x 128 x 512, B in registers, pipelined A LDS ----
        uint4 Acur = sA[lane];
        #pragma unroll
        for (int kt = 0; kt < 32; kt++) {
            uint4 Anext;
            if (kt < 31) Anext = sA[(kt + 1) * 32 + lane];
            if (kt & 1) {
                mma16816(a0o, Acur, wb_[kt].x, wb_[kt].y);
                mma16816(a1o, Acur, wb_[kt].z, wb_[kt].w);
            } else {
                mma16816(a0e, Acur, wb_[kt].x, wb_[kt].y);
                mma16816(a1e, Acur, wb_[kt].z, wb_[kt].w);
            }
            Acur = Anext;
        }

        // ---- merge chains + epilogue: 2 cells ----
        {
            float f, u, g, o;
            f = sigf(a0e[0] + a0o[0]); u = sigf(a0e[1] + a0o[1]);
            g = tanh_fast(a1e[0] + a1o[0]); o = sigf(a1e[1] + a1o[1]);
            cs0 = f * cs0 + u * g;  hv0 = o * tanh_fast(cs0);
            f = sigf(a0e[2] + a0o[2]); u = sigf(a0e[3] + a0o[3]);
            g = tanh_fast(a1e[2] + a1o[2]); o = sigf(a1e[3] + a1o[3]);
            cs1 = f * cs1 + u * g;  hv1 = o * tanh_fast(cs1);
        }

        // ---- publish h(t+1) in A-frag order (must precede release) ----
        {
            const int wb2 = (t + 1) & 1;
            const int blk = (wb2 * 8 + bgrp) * 1024;
            size_t i0 = ((size_t)(blk + (hg >> 4) * 32 + rA * 4 + ((hg >> 1) & 3))) * 8
                        + (((hg >> 3) & 1) * 2) * 2 + (hg & 1);
            hf16[i0] = __float2half(hv0);
            hf16[i0 + 2] = __float2half(hv1);
        }

        asm volatile("barrier.cluster.arrive.release.aligned;" ::: "memory");

        // ---- under the barrier wait: out stores + P(t+1) prefetch ----
        out[(size_t)t * (BB * HH) + (size_t)(bb + rA) * HH + hg] = hv0;
        out[(size_t)t * (BB * HH) + (size_t)(bb + rA + 8) * HH + hg] = hv1;
        if (t + 1 < TT) {
            const __half* p0 = P0 + (size_t)(t + 1) * 2048;
            const __half* p8 = P8 + (size_t)(t + 1) * 2048;
            pv[0] = __half2float(__ldg(p0 + hg));
            pv[1] = __half2float(__ldg(p0 + 512 + hg));
            pv[2] = __half2float(__ldg(p8 + hg));
            pv[3] = __half2float(__ldg(p8 + 512 + hg));
            pv[4] = __half2float(__ldg(p0 + 1024 + hg));
            pv[5] = __half2float(__ldg(p0 + 1536 + hg));
            pv[6] = __half2float(__ldg(p8 + 1024 + hg));
            pv[7] = __half2float(__ldg(p8 + 1536 + hg));
        }

        asm volatile("barrier.cluster.wait.acquire.aligned;" ::: "memory");
    }

    // ---- final h, c ----
    {
        const size_t OUT_H = (size_t)TT * BB * HH;
        const size_t OUT_C = OUT_H + (size_t)BB * HH;
        size_t b0 = (size_t)(bb + rA) * HH + hg;
        size_t b1 = (size_t)(bb + rA + 8) * HH + hg;
        out[OUT_H + b0] = hv0;  out[OUT_H + b1] = hv1;
        out[OUT_C + b0] = cs0;  out[OUT_C + b1] = cs1;
    }
}

// ---------------- launcher ----------------

extern "C" void kernel_launch(void* const* d_in, const int* in_sizes, int n_in,
                              void* d_out, int out_size) {
    (void)in_sizes; (void)n_in; (void)out_size;
    const float* x  = (const float*)d_in[0];
    const float* Wf = (const float*)d_in[1];
    const float* bf = (const float*)d_in[2];
    const float* Wu = (const float*)d_in[3];
    const float* bu = (const float*)d_in[4];
    const float* Wc = (const float*)d_in[5];
    const float* bc = (const float*)d_in[6];
    const float* Wo = (const float*)d_in[7];
    const float* bo = (const float*)d_in[8];
    float* out = (float*)d_out;

    cudaFuncSetAttribute(gemm_kernel, cudaFuncAttributeMaxDynamicSharedMemorySize, GM_SMEM);
    cudaFuncSetAttribute(lstm_kernel, cudaFuncAttributeMaxDynamicSharedMemorySize, L_SMEM);
    cudaFuncSetAttribute(lstm_kernel, cudaFuncAttributeNonPortableClusterSizeAllowed, 1);

    pack_kernel<<<640, 256>>>(Wf, Wu, Wc, Wo);
    gemm_kernel<<<dim3(16, 512), 256, GM_SMEM>>>(x, bf, bu, bc, bo);
    lstm_kernel<<<BB, 256, L_SMEM>>>(out);
}